// round 14
// baseline (speedup 1.0000x reference)
#include <cuda_runtime.h>
#include <cstdint>

#define En 64
#define An 8
#define Ln 2048
#define Dn 128
#define Hn 8
#define DKn 16
#define EA 512
#define SPLIT 4
#define RPS 512
#define TL 64

typedef unsigned long long ull;

__device__ __forceinline__ ull fma2(ull a, ull b, ull c) {
    ull d; asm("fma.rn.f32x2 %0, %1, %2, %3;" : "=l"(d) : "l"(a), "l"(b), "l"(c)); return d;
}
__device__ __forceinline__ ull mul2(ull a, ull b) {
    ull d; asm("mul.rn.f32x2 %0, %1, %2;" : "=l"(d) : "l"(a), "l"(b)); return d;
}
__device__ __forceinline__ ull pack2(float x, float y) {
    ull r; asm("mov.b64 %0, {%1,%2};" : "=l"(r) : "f"(x), "f"(y)); return r;
}
__device__ __forceinline__ float2 unpack2(ull v) {
    float2 r; asm("mov.b64 {%0,%1}, %2;" : "=f"(r.x), "=f"(r.y) : "l"(v)); return r;
}
__device__ __forceinline__ float ex2(float x) {
    float y; asm("ex2.approx.ftz.f32 %0, %1;" : "=f"(y) : "f"(x)); return y;
}

__device__ __align__(16) float g_Rk[EA * Hn * Dn];
__device__ __align__(16) float g_part[EA * SPLIT * 1040];  // m[8],Z[8],w[8][128]
__device__ int g_cnt[EA];

// ---------------- Kernel 1: fused query pipeline -> Rk ----------------
__global__ void prep(const float* __restrict__ gc, const float* __restrict__ dep,
                     const float* __restrict__ tbd, const float* __restrict__ loadv,
                     const float* __restrict__ Wqp, const float* __restrict__ Wq,
                     const float* __restrict__ Wk, const float* __restrict__ Wkp) {
    __shared__ float qsm[Dn];
    __shared__ float qhs[Hn * DKn];
    __shared__ float ut[Hn * 132];
    int b = blockIdx.x, e = b >> 3, a = b & 7, t = threadIdx.x;  // 256 threads

    if (t < Dn) {
        const float* s0 = gc + e * Dn;
        const float* s1 = dep + e * Dn;
        const float* s2 = tbd + e * Dn;
        float a0 = loadv[e * An + a] * Wqp[384 * Dn + t];
        float a1 = (float)a * Wqp[385 * Dn + t];
        float a2 = 0.f;
#pragma unroll 4
        for (int i = 0; i < Dn; i++) {
            a0 += s0[i] * Wqp[i * Dn + t];
            a1 += s1[i] * Wqp[(Dn + i) * Dn + t];
            a2 += s2[i] * Wqp[(2 * Dn + i) * Dn + t];
        }
        qsm[t] = (a0 + a1) + a2;
    }
    __syncthreads();
    if (t < Dn) {
        int h = t >> 4, k = t & 15;
        float acc = 0.f;
#pragma unroll 4
        for (int d = 0; d < Dn; d++) acc += qsm[d] * Wq[(h * Dn + d) * DKn + k];
        qhs[t] = acc;
    }
    __syncthreads();
    if (t < Dn) {
        const float SC = 0.25f * 1.4426950408889634f;
#pragma unroll
        for (int h = 0; h < Hn; h++) {
            const float* wkr = Wk + (h * Dn + t) * DKn;
            const float* qh = qhs + h * DKn;
            float acc = 0.f;
#pragma unroll
            for (int k = 0; k < DKn; k++) acc += qh[k] * wkr[k];
            ut[h * 132 + t] = SC * acc;
        }
    }
    __syncthreads();
    {
        int i = t >> 1, half = t & 1;
        const float* wrow = Wkp + i * Dn + 64 * half;
        float acc[Hn];
#pragma unroll
        for (int h = 0; h < Hn; h++) acc[h] = 0.f;
#pragma unroll
        for (int p = 0; p < 4; p++) {
            float4 v0 = *(const float4*)(wrow + 16 * p);
            float4 v1 = *(const float4*)(wrow + 16 * p + 4);
            float4 v2 = *(const float4*)(wrow + 16 * p + 8);
            float4 v3 = *(const float4*)(wrow + 16 * p + 12);
#pragma unroll
            for (int h = 0; h < Hn; h++) {
                const float* u = ut + h * 132 + 64 * half + 16 * p;
                acc[h] += v0.x*u[0] + v0.y*u[1] + v0.z*u[2] + v0.w*u[3]
                        + v1.x*u[4] + v1.y*u[5] + v1.z*u[6] + v1.w*u[7]
                        + v2.x*u[8] + v2.y*u[9] + v2.z*u[10] + v2.w*u[11]
                        + v3.x*u[12] + v3.y*u[13] + v3.z*u[14] + v3.w*u[15];
            }
        }
#pragma unroll
        for (int h = 0; h < Hn; h++) acc[h] += __shfl_xor_sync(0xffffffffu, acc[h], 1);
        if (!half)
#pragma unroll
            for (int h = 0; h < Hn; h++) g_Rk[((size_t)b * Hn + h) * Dn + i] = acc[h];
    }
}

// ---------------- Kernel 2: main, 256 thr, per-warp stripes, emb read ONCE per pass -------
// smem floats: [0,16384) 8 warps x 2 bufs x 8 rows x 128 | pd 8 warps x 128 @16384
//              sMZ 8 warps x 16 @17408 | total 17536 floats (70.1KB)
#define SM_PD 16384
#define SM_MZ 17408
#define SMEM_BYTES (17536 * 4)

__global__ __launch_bounds__(256, 2)
void decoder_main(const float* __restrict__ emb, const int* __restrict__ lens,
                  const float* __restrict__ Wvp, const float* __restrict__ Wv,
                  const float* __restrict__ Wo, float* __restrict__ out) {
    extern __shared__ float sm[];
    __shared__ int sflag;

    int blk = blockIdx.x, b = blk >> 2, sp = blk & 3, t = threadIdx.x;
    int wrp = t >> 5, lane = t & 31;
    int myh = (lane >> 2) & 7;                 // head this lane's softmax state tracks
    int b2 = (lane >> 2) & 1, b3 = (lane >> 3) & 1, b4 = (lane >> 4) & 1;
    int len = lens[b];
    int cnt = min(len - sp * RPS, RPS);
    int ntiles = (cnt > 0) ? ((cnt + TL - 1) >> 6) : 0;
    const float* embp = emb + (size_t)b * (Ln * Dn) + (size_t)sp * RPS * Dn;

    float* wbuf = sm + wrp * 2048;             // 2 bufs x 8 rows x 128
    float* pd   = sm + SM_PD + wrp * 128;      // [8 rows][8 heads float2-dup]
    float* sMZ  = sm + SM_MZ;
    uint32_t wdst = (uint32_t)__cvta_generic_to_shared(wbuf) + (uint32_t)lane * 16;

    // Rk: per head h, this lane's 4 floats (4*lane..+3) -> rkx/rky
    ull rkx[Hn], rky[Hn];
#pragma unroll
    for (int h = 0; h < Hn; h++) {
        ulonglong2 v = *(const ulonglong2*)(g_Rk + ((size_t)b * Hn + h) * Dn + 4 * lane);
        rkx[h] = v.x; rky[h] = v.y;
    }

    float m = -30000.f, Z = 0.f;
    ull w0[Hn], w1[Hn];
#pragma unroll
    for (int i = 0; i < Hn; i++) { w0[i] = 0ull; w1[i] = 0ull; }

#define LD_STRIPE(tt, bufk)                                                              \
    do {                                                                                  \
        const float* _s = embp + (size_t)((tt) * TL + wrp * 8) * Dn + lane * 4;           \
        uint32_t _d = wdst + (uint32_t)(bufk) * 4096;                                     \
        _Pragma("unroll")                                                                 \
        for (int _i = 0; _i < 8; _i++)                                                    \
            asm volatile("cp.async.cg.shared.global [%0], [%1], 16;\n"                    \
                         :: "r"(_d + _i * 512), "l"(_s + _i * Dn) : "memory");            \
        asm volatile("cp.async.commit_group;\n" ::: "memory");                            \
    } while (0)

    if (ntiles > 0) {
        LD_STRIPE(0, 0);
        if (ntiles > 1) LD_STRIPE(1, 1);

        for (int tt = 0; tt < ntiles; tt++) {
            if (tt + 1 < ntiles) asm volatile("cp.async.wait_group 1;\n" ::: "memory");
            else                 asm volatile("cp.async.wait_group 0;\n" ::: "memory");
            __syncwarp();
            const float* tb = wbuf + (tt & 1) * 1024;
            int base = tt * TL + wrp * 8;

            // ---- score: emb row read ONCE; 8 head partials; 9-shfl reduce-scatter ----
            float s8[8];
#pragma unroll
            for (int i = 0; i < 8; i++) {
                ulonglong2 ev = *(const ulonglong2*)(tb + i * Dn + 4 * lane);
                float v[8];
#pragma unroll
                for (int h = 0; h < Hn; h++) {
                    ull acc = mul2(ev.x, rkx[h]);
                    acc = fma2(ev.y, rky[h], acc);
                    float2 f2 = unpack2(acc);
                    v[h] = f2.x + f2.y;
                }
                // stage xor16 (head bit2 <- b4)
#pragma unroll
                for (int j = 0; j < 4; j++) {
                    float x = b4 ? v[j] : v[j + 4];
                    float y = __shfl_xor_sync(0xffffffffu, x, 16);
                    v[j] = (b4 ? v[j + 4] : v[j]) + y;
                }
                // stage xor8 (head bit1 <- b3)
#pragma unroll
                for (int j = 0; j < 2; j++) {
                    float x = b3 ? v[j] : v[j + 2];
                    float y = __shfl_xor_sync(0xffffffffu, x, 8);
                    v[j] = (b3 ? v[j + 2] : v[j]) + y;
                }
                // stage xor4 (head bit0 <- b2)
                {
                    float x = b2 ? v[0] : v[1];
                    float y = __shfl_xor_sync(0xffffffffu, x, 4);
                    v[0] = (b2 ? v[1] : v[0]) + y;
                }
                // finish sum over lane bits 0,1
                v[0] += __shfl_xor_sync(0xffffffffu, v[0], 1);
                v[0] += __shfl_xor_sync(0xffffffffu, v[0], 2);
                s8[i] = (base + i < cnt) ? v[0] : -1e30f;
            }

            // ---- per-lane online softmax for head myh (4x duplicated) ----
            float tm = s8[0];
#pragma unroll
            for (int i = 1; i < 8; i++) tm = fmaxf(tm, s8[i]);
            float mn = fmaxf(m, tm);
            float f = ex2(m - mn);
            m = mn;
            float zs = 0.f;
#pragma unroll
            for (int i = 0; i < 8; i++) {
                s8[i] = (s8[i] > -1e29f) ? ex2(s8[i] - mn) : 0.f;
                zs += s8[i];
            }
            Z = Z * f + zs;

            // stash p duplicated: one lane per head writes all 8 rows
            if ((lane & 3) == 0) {
#pragma unroll
                for (int i = 0; i < 8; i++)
                    *(float2*)(pd + i * 16 + 2 * myh) = make_float2(s8[i], s8[i]);
            }
            __syncwarp();

            // ---- rescale + accumulate (emb row read once more) ----
#pragma unroll
            for (int h = 0; h < Hn; h++) {
                float fh = __shfl_sync(0xffffffffu, f, 4 * h);
                ull fp = pack2(fh, fh);
                w0[h] = mul2(w0[h], fp);
                w1[h] = mul2(w1[h], fp);
            }
#pragma unroll
            for (int i = 0; i < 8; i++) {
                ulonglong2 ev = *(const ulonglong2*)(tb + i * Dn + 4 * lane);
                const ulonglong2* pdr = (const ulonglong2*)(pd + i * 16);
#pragma unroll
                for (int j = 0; j < 4; j++) {
                    ulonglong2 pp = pdr[j];   // heads 2j, 2j+1 (broadcast)
                    w0[2 * j]     = fma2(pp.x, ev.x, w0[2 * j]);
                    w1[2 * j]     = fma2(pp.x, ev.y, w1[2 * j]);
                    w0[2 * j + 1] = fma2(pp.y, ev.x, w0[2 * j + 1]);
                    w1[2 * j + 1] = fma2(pp.y, ev.y, w1[2 * j + 1]);
                }
            }
            __syncwarp();
            if (tt + 2 < ntiles) LD_STRIPE(tt + 2, tt & 1);
        }
    }

    // ---- CTA merge of 8 per-warp partials ----
    if ((lane & 3) == 0) { sMZ[wrp * 16 + myh] = m; sMZ[wrp * 16 + 8 + myh] = Z; }
    __syncthreads();
    {
        ulonglong2* Wm = (ulonglong2*)sm;  // [8 warps][8 heads][32 lanes] x 16B = 32KB
#pragma unroll
        for (int h = 0; h < Hn; h++) {
            ulonglong2 v; v.x = w0[h]; v.y = w1[h];
            Wm[(wrp * 8 + h) * 32 + lane] = v;
        }
    }
    __syncthreads();
    {
        int h2 = t >> 5, dq = t & 31;
        float mc = sMZ[h2];
#pragma unroll
        for (int wv = 1; wv < 8; wv++) mc = fmaxf(mc, sMZ[wv * 16 + h2]);
        float fw[8], Zc = 0.f;
#pragma unroll
        for (int wv = 0; wv < 8; wv++) {
            fw[wv] = ex2(sMZ[wv * 16 + h2] - mc);
            Zc += sMZ[wv * 16 + 8 + h2] * fw[wv];
        }
        const float4* Wmf = (const float4*)sm;
        float4 acc = make_float4(0.f, 0.f, 0.f, 0.f);
#pragma unroll
        for (int wv = 0; wv < 8; wv++) {
            float4 v = Wmf[(wv * 8 + h2) * 32 + dq];
            acc.x += fw[wv] * v.x; acc.y += fw[wv] * v.y;
            acc.z += fw[wv] * v.z; acc.w += fw[wv] * v.w;
        }
        float* gp = g_part + (size_t)blk * 1040;
        *(float4*)(gp + 16 + h2 * Dn + 4 * dq) = acc;
        if (dq == 0) { gp[h2] = mc; gp[8 + h2] = Zc; }
    }
    __syncthreads();

    // ---- last-arriver combine + epilogue ----
    __threadfence();
    if (t == 0) {
        int r = atomicAdd(&g_cnt[b], 1);
        sflag = (r == SPLIT - 1);
        if (r == SPLIT - 1) g_cnt[b] = 0;
    }
    __syncthreads();
    if (!sflag) return;
    __threadfence();

    int a = b & 7;
    float* cc   = sm;
    float* wfs  = sm + 32;
    float* vmid = sm + 32 + Hn * Dn;
    float* sCtx = vmid + Hn * Dn;
    const float* P0 = g_part + (size_t)(b * SPLIT) * 1040;
    const float* P1 = P0 + 1040;
    const float* P2 = P1 + 1040;
    const float* P3 = P2 + 1040;

    if (t < 8) {
        float m0 = P0[t], m1 = P1[t], m2 = P2[t], m3 = P3[t];
        float mm = fmaxf(fmaxf(m0, m1), fmaxf(m2, m3));
        float a0 = ex2(m0 - mm), a1 = ex2(m1 - mm), a2 = ex2(m2 - mm), a3 = ex2(m3 - mm);
        float inv = 1.f / (P0[8 + t] * a0 + P1[8 + t] * a1 + P2[8 + t] * a2 + P3[8 + t] * a3);
        cc[t] = a0 * inv; cc[8 + t] = a1 * inv; cc[16 + t] = a2 * inv; cc[24 + t] = a3 * inv;
    }
    __syncthreads();
    if (t < 128) {
#pragma unroll
        for (int hh = 0; hh < Hn; hh++) {
            int off = 16 + hh * Dn + t;
            wfs[hh * Dn + t] = P0[off] * cc[hh] + P1[off] * cc[8 + hh]
                             + P2[off] * cc[16 + hh] + P3[off] * cc[24 + hh];
        }
    }
    __syncthreads();
    if (t < 128) {
        float acc[Hn];
        float bias = (float)a * Wvp[Dn * Dn + t];
#pragma unroll
        for (int hh = 0; hh < Hn; hh++) acc[hh] = bias;
#pragma unroll 4
        for (int i = 0; i < Dn; i++) {
            float wv = Wvp[i * Dn + t];
#pragma unroll
            for (int hh = 0; hh < Hn; hh++) acc[hh] += wfs[hh * Dn + i] * wv;
        }
#pragma unroll
        for (int hh = 0; hh < Hn; hh++) vmid[hh * Dn + t] = acc[hh];
    }
    __syncthreads();
    if (t < 128) {
        int hh = t >> 4, k = t & 15;
        const float* wvr = Wv + hh * Dn * DKn + k;
        const float* vm = vmid + hh * Dn;
        float acc = 0.f;
#pragma unroll 4
        for (int d = 0; d < Dn; d++) acc += vm[d] * wvr[d * DKn];
        sCtx[t] = acc;
    }
    __syncthreads();
    if (t < 128) {
        float acc = 0.f;
#pragma unroll 4
        for (int j = 0; j < Hn * DKn; j++) acc += sCtx[j] * Wo[j * Dn + t];
        out[(size_t)b * Dn + t] = acc;
    }
}

// ---------------------------------------------------------------------------
extern "C" void kernel_launch(void* const* d_in, const int* in_sizes, int n_in,
                              void* d_out, int out_size) {
    const float* gc      = (const float*)d_in[0];
    const float* depot   = (const float*)d_in[1];
    const float* tbd     = (const float*)d_in[2];
    const float* loadv   = (const float*)d_in[3];
    const float* emb     = (const float*)d_in[4];
    const int*   lens    = (const int*)  d_in[5];
    const float* Wq_proj = (const float*)d_in[6];
    const float* Wk_proj = (const float*)d_in[7];
    const float* Wv_proj = (const float*)d_in[8];
    const float* Wq      = (const float*)d_in[9];
    const float* Wk      = (const float*)d_in[10];
    const float* Wv      = (const float*)d_in[11];
    const float* Wo      = (const float*)d_in[12];
    float* out = (float*)d_out;

    prep<<<EA, 256>>>(gc, depot, tbd, loadv, Wq_proj, Wq, Wk, Wk_proj);

    cudaFuncSetAttribute(decoder_main, cudaFuncAttributeMaxDynamicSharedMemorySize, SMEM_BYTES);
    decoder_main<<<EA * SPLIT, 256, SMEM_BYTES>>>(emb, lens, Wv_proj, Wv, Wo, out);
}

// round 15
// speedup vs baseline: 1.5432x; 1.5432x over previous
#include <cuda_runtime.h>
#include <cstdint>

#define En 64
#define An 8
#define Ln 2048
#define Dn 128
#define Hn 8
#define DKn 16
#define EA 512
#define SPLIT 8
#define RPS 256
#define TLC 32             // CTA tile rows (4 warps x 8)
#define WSTR 132           // padded row stride inside a warp tile (floats)
#define WTILE (2 * 8 * WSTR)   // 2112 floats per warp (two 8-row buffers)

typedef unsigned long long ull;

__device__ __forceinline__ ull fma2(ull a, ull b, ull c) {
    ull d; asm("fma.rn.f32x2 %0, %1, %2, %3;" : "=l"(d) : "l"(a), "l"(b), "l"(c)); return d;
}
__device__ __forceinline__ ull mul2(ull a, ull b) {
    ull d; asm("mul.rn.f32x2 %0, %1, %2;" : "=l"(d) : "l"(a), "l"(b)); return d;
}
__device__ __forceinline__ ull pack2(float x, float y) {
    ull r; asm("mov.b64 %0, {%1,%2};" : "=l"(r) : "f"(x), "f"(y)); return r;
}
__device__ __forceinline__ float2 unpack2(ull v) {
    float2 r; asm("mov.b64 {%0,%1}, %2;" : "=f"(r.x), "=f"(r.y) : "l"(v)); return r;
}
__device__ __forceinline__ float ex2(float x) {
    float y; asm("ex2.approx.ftz.f32 %0, %1;" : "=f"(y) : "f"(x)); return y;
}

__device__ __align__(16) float g_Rk[EA * Hn * Dn];
__device__ __align__(16) float g_part[EA * SPLIT * 1040];  // m[8],Z[8],w[8][128]
__device__ int g_cnt[EA];

// ---------------- Kernel 1: fused query pipeline -> Rk ----------------
__global__ void prep(const float* __restrict__ gc, const float* __restrict__ dep,
                     const float* __restrict__ tbd, const float* __restrict__ loadv,
                     const float* __restrict__ Wqp, const float* __restrict__ Wq,
                     const float* __restrict__ Wk, const float* __restrict__ Wkp) {
    __shared__ float qsm[Dn];
    __shared__ float qhs[Hn * DKn];
    __shared__ float ut[Hn * 132];
    int b = blockIdx.x, e = b >> 3, a = b & 7, t = threadIdx.x;  // 256 threads

    if (t < Dn) {
        const float* s0 = gc + e * Dn;
        const float* s1 = dep + e * Dn;
        const float* s2 = tbd + e * Dn;
        float a0 = loadv[e * An + a] * Wqp[384 * Dn + t];
        float a1 = (float)a * Wqp[385 * Dn + t];
        float a2 = 0.f;
#pragma unroll 4
        for (int i = 0; i < Dn; i++) {
            a0 += s0[i] * Wqp[i * Dn + t];
            a1 += s1[i] * Wqp[(Dn + i) * Dn + t];
            a2 += s2[i] * Wqp[(2 * Dn + i) * Dn + t];
        }
        qsm[t] = (a0 + a1) + a2;
    }
    __syncthreads();
    if (t < Dn) {
        int h = t >> 4, k = t & 15;
        float acc = 0.f;
#pragma unroll 4
        for (int d = 0; d < Dn; d++) acc += qsm[d] * Wq[(h * Dn + d) * DKn + k];
        qhs[t] = acc;
    }
    __syncthreads();
    if (t < Dn) {
        const float SC = 0.25f * 1.4426950408889634f;
#pragma unroll
        for (int h = 0; h < Hn; h++) {
            const float* wkr = Wk + (h * Dn + t) * DKn;
            const float* qh = qhs + h * DKn;
            float acc = 0.f;
#pragma unroll
            for (int k = 0; k < DKn; k++) acc += qh[k] * wkr[k];
            ut[h * 132 + t] = SC * acc;
        }
    }
    __syncthreads();
    {
        int i = t >> 1, half = t & 1;
        const float* wrow = Wkp + i * Dn + 64 * half;
        float acc[Hn];
#pragma unroll
        for (int h = 0; h < Hn; h++) acc[h] = 0.f;
#pragma unroll
        for (int p = 0; p < 4; p++) {
            float4 v0 = *(const float4*)(wrow + 16 * p);
            float4 v1 = *(const float4*)(wrow + 16 * p + 4);
            float4 v2 = *(const float4*)(wrow + 16 * p + 8);
            float4 v3 = *(const float4*)(wrow + 16 * p + 12);
#pragma unroll
            for (int h = 0; h < Hn; h++) {
                const float* u = ut + h * 132 + 64 * half + 16 * p;
                acc[h] += v0.x*u[0] + v0.y*u[1] + v0.z*u[2] + v0.w*u[3]
                        + v1.x*u[4] + v1.y*u[5] + v1.z*u[6] + v1.w*u[7]
                        + v2.x*u[8] + v2.y*u[9] + v2.z*u[10] + v2.w*u[11]
                        + v3.x*u[12] + v3.y*u[13] + v3.z*u[14] + v3.w*u[15];
            }
        }
#pragma unroll
        for (int h = 0; h < Hn; h++) acc[h] += __shfl_xor_sync(0xffffffffu, acc[h], 1);
        if (!half)
#pragma unroll
            for (int h = 0; h < Hn; h++) g_Rk[((size_t)b * Hn + h) * Dn + i] = acc[h];
    }
}

// ---------------- Kernel 2: main. 128 thr (4 warps), occ 5, champion loop ----------------
// smem floats: [0,8448) 4 warp-tiles (2 bufs x 8 rows x 132) | pd 4x128 @8448
//              sMZ 4x16 @8960 | total 9024 floats (36.1KB); epilogue aliases sm[0]
#define SM_PD 8448
#define SM_MZ 8960
#define SMEM_BYTES (9024 * 4)

__global__ __launch_bounds__(128, 5)
void decoder_main(const float* __restrict__ emb, const int* __restrict__ lens,
                  const float* __restrict__ Wvp, const float* __restrict__ Wv,
                  const float* __restrict__ Wo, float* __restrict__ out) {
    extern __shared__ float sm[];
    __shared__ int sflag;

    int blk = blockIdx.x, b = blk >> 3, sp = blk & 7, t = threadIdx.x;
    int wrp = t >> 5, lane = t & 31;
    int h = lane & 7, q = lane >> 3;
    int len = lens[b];
    int cnt = min(len - sp * RPS, RPS);
    int ntiles = (cnt > 0) ? ((cnt + TLC - 1) >> 5) : 0;
    const float* embp = emb + (size_t)b * (Ln * Dn) + (size_t)sp * RPS * Dn;

    float* wbuf = sm + wrp * WTILE;
    float* pd   = sm + SM_PD + wrp * 128;      // [8 rows][8 heads float2-dup]
    float* sMZ  = sm + SM_MZ;
    uint32_t wdst = (uint32_t)__cvta_generic_to_shared(wbuf) + (uint32_t)lane * 16;

    // Rk registers: lane (h,q) holds floats {16j+4q..+3} of head h
    ull rk[16];
    {
        const float* rbase = g_Rk + ((size_t)b * Hn + h) * Dn + 4 * q;
#pragma unroll
        for (int j = 0; j < 8; j++) {
            ulonglong2 v = *(const ulonglong2*)(rbase + 16 * j);
            rk[2 * j] = v.x; rk[2 * j + 1] = v.y;
        }
    }

    float m = -30000.f, Z = 0.f;
    ull w0[Hn], w1[Hn];
#pragma unroll
    for (int i = 0; i < Hn; i++) { w0[i] = 0ull; w1[i] = 0ull; }

#define LD_STRIPE(tt, bufk)                                                              \
    do {                                                                                  \
        const float* _s = embp + (size_t)((tt) * TLC + wrp * 8) * Dn + lane * 4;          \
        uint32_t _d = wdst + (uint32_t)(bufk) * (8 * WSTR * 4);                           \
        _Pragma("unroll")                                                                 \
        for (int _i = 0; _i < 8; _i++)                                                    \
            asm volatile("cp.async.cg.shared.global [%0], [%1], 16;\n"                    \
                         :: "r"(_d + _i * (WSTR * 4)), "l"(_s + _i * Dn) : "memory");     \
        asm volatile("cp.async.commit_group;\n" ::: "memory");                            \
    } while (0)

    if (ntiles > 0) {
        LD_STRIPE(0, 0);
        if (ntiles > 1) LD_STRIPE(1, 1);

        for (int tt = 0; tt < ntiles; tt++) {
            if (tt + 1 < ntiles) asm volatile("cp.async.wait_group 1;\n" ::: "memory");
            else                 asm volatile("cp.async.wait_group 0;\n" ::: "memory");
            __syncwarp();
            const float* tb = wbuf + (tt & 1) * (8 * WSTR);
            int base = tt * TLC + wrp * 8;

            // score: 8 rows; lane (h,q); full dot after 2 shfls
            float s8[8];
#pragma unroll
            for (int i = 0; i < 8; i++) {
                const ulonglong2* rp = (const ulonglong2*)(tb + i * WSTR + 4 * q);
                ull a0 = 0ull, a1 = 0ull;
#pragma unroll
                for (int j = 0; j < 8; j++) {
                    ulonglong2 ev = rp[4 * j];
                    a0 = fma2(ev.x, rk[2 * j], a0);
                    a1 = fma2(ev.y, rk[2 * j + 1], a1);
                }
                float2 fa = unpack2(a0), fb = unpack2(a1);
                float sv = (fa.x + fa.y) + (fb.x + fb.y);
                sv += __shfl_xor_sync(0xffffffffu, sv, 8);
                sv += __shfl_xor_sync(0xffffffffu, sv, 16);
                s8[i] = (base + i < cnt) ? sv : -1e30f;
            }

            // per-warp online softmax (per-lane state for head h, dup over q)
            float tm = s8[0];
#pragma unroll
            for (int i = 1; i < 8; i++) tm = fmaxf(tm, s8[i]);
            float mn = fmaxf(m, tm);
            float f = ex2(m - mn);
            m = mn;
            float zs = 0.f;
#pragma unroll
            for (int i = 0; i < 8; i++) {
                s8[i] = (s8[i] > -1e29f) ? ex2(s8[i] - mn) : 0.f;
                zs += s8[i];
            }
            Z = Z * f + zs;

            // stash p duplicated: lane (h,q) writes rows q and q+4
            *(float2*)(pd + q * 16 + 2 * h)       = make_float2(s8[q], s8[q]);
            *(float2*)(pd + (q + 4) * 16 + 2 * h) = make_float2(s8[q + 4], s8[q + 4]);
            __syncwarp();

            // rescale + accumulate (lane = dq covers floats 4*lane..+3)
#pragma unroll
            for (int hh = 0; hh < Hn; hh++) {
                float fh = __shfl_sync(0xffffffffu, f, hh);
                ull fp = pack2(fh, fh);
                w0[hh] = mul2(w0[hh], fp);
                w1[hh] = mul2(w1[hh], fp);
            }
#pragma unroll
            for (int i = 0; i < 8; i++) {
                ulonglong2 ev = *(const ulonglong2*)(tb + i * WSTR + 4 * lane);
                const ull* pdr = (const ull*)(pd + i * 16);
#pragma unroll
                for (int hh = 0; hh < Hn; hh++) {
                    w0[hh] = fma2(pdr[hh], ev.x, w0[hh]);
                    w1[hh] = fma2(pdr[hh], ev.y, w1[hh]);
                }
            }
            __syncwarp();
            if (tt + 2 < ntiles) LD_STRIPE(tt + 2, tt & 1);
        }
    }

    // ---- CTA merge of 4 per-warp partials ----
    if (q == 0) { sMZ[wrp * 16 + h] = m; sMZ[wrp * 16 + 8 + h] = Z; }
    __syncthreads();
    {
        ulonglong2* Wm = (ulonglong2*)sm;  // [4 warps][8 heads][32 lanes] x 16B = 16KB
#pragma unroll
        for (int hh = 0; hh < Hn; hh++) {
            ulonglong2 v; v.x = w0[hh]; v.y = w1[hh];
            Wm[(wrp * 8 + hh) * 32 + lane] = v;
        }
    }
    __syncthreads();
    {
        int h2 = t >> 4, g = t & 15;  // head, 2 quads each
        float mc = sMZ[h2];
#pragma unroll
        for (int wv = 1; wv < 4; wv++) mc = fmaxf(mc, sMZ[wv * 16 + h2]);
        float fw[4], Zc = 0.f;
#pragma unroll
        for (int wv = 0; wv < 4; wv++) {
            fw[wv] = ex2(sMZ[wv * 16 + h2] - mc);
            Zc += sMZ[wv * 16 + 8 + h2] * fw[wv];
        }
        const float4* Wmf = (const float4*)sm;
        float* gp = g_part + (size_t)blk * 1040;
#pragma unroll
        for (int part = 0; part < 2; part++) {
            int dq = g + 16 * part;
            float4 acc = make_float4(0.f, 0.f, 0.f, 0.f);
#pragma unroll
            for (int wv = 0; wv < 4; wv++) {
                float4 v = Wmf[(wv * 8 + h2) * 32 + dq];
                acc.x += fw[wv] * v.x; acc.y += fw[wv] * v.y;
                acc.z += fw[wv] * v.z; acc.w += fw[wv] * v.w;
            }
            *(float4*)(gp + 16 + h2 * Dn + 4 * dq) = acc;
        }
        if (g == 0) { gp[h2] = mc; gp[8 + h2] = Zc; }
    }
    __syncthreads();

    // ---- last-arriver combine + epilogue for this (e,a) ----
    __threadfence();
    if (t == 0) {
        int r = atomicAdd(&g_cnt[b], 1);
        sflag = (r == SPLIT - 1);
        if (r == SPLIT - 1) g_cnt[b] = 0;
    }
    __syncthreads();
    if (!sflag) return;
    __threadfence();

    int a = b & 7;
    float* cc   = sm;                 // [8 splits][8 heads]
    float* wfs  = sm + 64;            // [8][128]
    float* vmid = sm + 64 + Hn * Dn;
    float* sCtx = vmid + Hn * Dn;
    const float* Pb = g_part + (size_t)(b * SPLIT) * 1040;

    if (t < 8) {
        float mm = -1e30f;
#pragma unroll
        for (int s = 0; s < SPLIT; s++) mm = fmaxf(mm, Pb[s * 1040 + t]);
        float as[SPLIT], Zt = 0.f;
#pragma unroll
        for (int s = 0; s < SPLIT; s++) {
            as[s] = ex2(Pb[s * 1040 + t] - mm);
            Zt += Pb[s * 1040 + 8 + t] * as[s];
        }
        float inv = 1.f / Zt;
#pragma unroll
        for (int s = 0; s < SPLIT; s++) cc[s * 8 + t] = as[s] * inv;
    }
    __syncthreads();
    {
#pragma unroll
        for (int hh = 0; hh < Hn; hh++) {
            int off = 16 + hh * Dn + t;
            float acc = 0.f;
#pragma unroll
            for (int s = 0; s < SPLIT; s++) acc += Pb[s * 1040 + off] * cc[s * 8 + hh];
            wfs[hh * Dn + t] = acc;
        }
    }
    __syncthreads();
    {  // vmid[h][t] = wfs[h] @ Wvp + a*Wvp[128]
        float acc[Hn];
        float bias = (float)a * Wvp[Dn * Dn + t];
#pragma unroll
        for (int hh = 0; hh < Hn; hh++) acc[hh] = bias;
#pragma unroll 4
        for (int i = 0; i < Dn; i++) {
            float wv = Wvp[i * Dn + t];
#pragma unroll
            for (int hh = 0; hh < Hn; hh++) acc[hh] += wfs[hh * Dn + i] * wv;
        }
#pragma unroll
        for (int hh = 0; hh < Hn; hh++) vmid[hh * Dn + t] = acc[hh];
    }
    __syncthreads();
    {  // ctx[h][k]
        int hh = t >> 4, k = t & 15;
        const float* wvr = Wv + hh * Dn * DKn + k;
        const float* vm = vmid + hh * Dn;
        float acc = 0.f;
#pragma unroll 4
        for (int d = 0; d < Dn; d++) acc += vm[d] * wvr[d * DKn];
        sCtx[t] = acc;
    }
    __syncthreads();
    {  // out = ctx @ Wo
        float acc = 0.f;
#pragma unroll 4
        for (int j = 0; j < Hn * DKn; j++) acc += sCtx[j] * Wo[j * Dn + t];
        out[(size_t)b * Dn + t] = acc;
    }
}

// ---------------------------------------------------------------------------
extern "C" void kernel_launch(void* const* d_in, const int* in_sizes, int n_in,
                              void* d_out, int out_size) {
    const float* gc      = (const float*)d_in[0];
    const float* depot   = (const float*)d_in[1];
    const float* tbd     = (const float*)d_in[2];
    const float* loadv   = (const float*)d_in[3];
    const float* emb     = (const float*)d_in[4];
    const int*   lens    = (const int*)  d_in[5];
    const float* Wq_proj = (const float*)d_in[6];
    const float* Wk_proj = (const float*)d_in[7];
    const float* Wv_proj = (const float*)d_in[8];
    const float* Wq      = (const float*)d_in[9];
    const float* Wk      = (const float*)d_in[10];
    const float* Wv      = (const float*)d_in[11];
    const float* Wo      = (const float*)d_in[12];
    float* out = (float*)d_out;

    prep<<<EA, 256>>>(gc, depot, tbd, loadv, Wq_proj, Wq, Wk, Wk_proj);

    cudaFuncSetAttribute(decoder_main, cudaFuncAttributeMaxDynamicSharedMemorySize, SMEM_BYTES);
    decoder_main<<<EA * SPLIT, 128, SMEM_BYTES>>>(emb, lens, Wv_proj, Wv, Wo, out);
}

// round 16
// speedup vs baseline: 1.8410x; 1.1930x over previous
#include <cuda_runtime.h>
#include <cstdint>

#define En 64
#define An 8
#define Ln 2048
#define Dn 128
#define Hn 8
#define DKn 16
#define EA 512
#define SPLIT 8
#define RPS 256
#define TLC 32             // CTA tile rows (4 warps x 8)
#define WSTR 132           // padded row stride inside a warp tile (floats)
#define WTILE (2 * 8 * WSTR)   // 2112 floats per warp (two 8-row buffers)

typedef unsigned long long ull;

__device__ __forceinline__ ull fma2(ull a, ull b, ull c) {
    ull d; asm("fma.rn.f32x2 %0, %1, %2, %3;" : "=l"(d) : "l"(a), "l"(b), "l"(c)); return d;
}
__device__ __forceinline__ ull mul2(ull a, ull b) {
    ull d; asm("mul.rn.f32x2 %0, %1, %2;" : "=l"(d) : "l"(a), "l"(b)); return d;
}
__device__ __forceinline__ ull pack2(float x, float y) {
    ull r; asm("mov.b64 %0, {%1,%2};" : "=l"(r) : "f"(x), "f"(y)); return r;
}
__device__ __forceinline__ float2 unpack2(ull v) {
    float2 r; asm("mov.b64 {%0,%1}, %2;" : "=f"(r.x), "=f"(r.y) : "l"(v)); return r;
}
__device__ __forceinline__ float ex2(float x) {
    float y; asm("ex2.approx.ftz.f32 %0, %1;" : "=f"(y) : "f"(x)); return y;
}

__device__ __align__(16) float g_bq[En * Dn];              // agent-independent base query
__device__ __align__(16) float g_Gk[Hn * Dn * DKn];        // SC * (Wk_proj @ Wk[h])
__device__ __align__(16) float g_Rk[EA * Hn * Dn];
__device__ __align__(16) float g_part[EA * SPLIT * 1040];  // m[8],Z[8],w[8][128]
__device__ int g_cnt[EA];

// ---------------- Kernel A: per-e base query (blocks 0..63) + Gk build (blocks 64..71) ------
__global__ void prepA(const float* __restrict__ gc, const float* __restrict__ dep,
                      const float* __restrict__ tbd, const float* __restrict__ Wqp,
                      const float* __restrict__ Wk, const float* __restrict__ Wkp) {
    int blk = blockIdx.x, t = threadIdx.x;  // 256 threads
    if (blk < En) {
        if (t < Dn) {
            int e = blk;
            const float* s0 = gc + e * Dn;
            const float* s1 = dep + e * Dn;
            const float* s2 = tbd + e * Dn;
            float a0 = 0.f, a1 = 0.f, a2 = 0.f;
#pragma unroll 4
            for (int i = 0; i < Dn; i++) {
                a0 += s0[i] * Wqp[i * Dn + t];
                a1 += s1[i] * Wqp[(Dn + i) * Dn + t];
                a2 += s2[i] * Wqp[(2 * Dn + i) * Dn + t];
            }
            g_bq[blk * Dn + t] = (a0 + a1) + a2;
        }
    } else {
        // Gk[h][i][k] = SC * sum_d Wkp[i,d] * Wk[h,d,k]
        __shared__ float wks[Dn * DKn];
        int h = blk - En;
        for (int j = t; j < Dn * DKn; j += 256) wks[j] = Wk[h * Dn * DKn + j];
        __syncthreads();
        int i = t >> 1, half = t & 1;
        const float* wrow = Wkp + i * Dn + 64 * half;
        float acc[DKn];
#pragma unroll
        for (int k = 0; k < DKn; k++) acc[k] = 0.f;
#pragma unroll
        for (int p = 0; p < 16; p++) {
            float4 v = *(const float4*)(wrow + 4 * p);
            const float* w0 = wks + (64 * half + 4 * p) * DKn;
#pragma unroll
            for (int k = 0; k < DKn; k++)
                acc[k] += v.x * w0[k] + v.y * w0[DKn + k] + v.z * w0[2 * DKn + k] + v.w * w0[3 * DKn + k];
        }
#pragma unroll
        for (int k = 0; k < DKn; k++) acc[k] += __shfl_xor_sync(0xffffffffu, acc[k], 1);
        if (!half) {
            const float SC = 0.25f * 1.4426950408889634f;
            float* dst = g_Gk + (h * Dn + i) * DKn;
#pragma unroll
            for (int k = 0; k < DKn; k++) dst[k] = SC * acc[k];
        }
    }
}

// ---------------- Kernel B: per-(e,a): q -> qh -> Rk (via Gk) ----------------
__global__ void prepB(const float* __restrict__ loadv, const float* __restrict__ Wqp,
                      const float* __restrict__ Wq) {
    __shared__ float qsm[Dn];
    __shared__ float qhs[Hn * DKn];
    int b = blockIdx.x, e = b >> 3, a = b & 7, t = threadIdx.x;  // 128 threads

    qsm[t] = g_bq[e * Dn + t] + loadv[e * An + a] * Wqp[384 * Dn + t]
           + (float)a * Wqp[385 * Dn + t];
    __syncthreads();
    {
        int h = t >> 4, k = t & 15;
        float acc = 0.f;
#pragma unroll 4
        for (int d = 0; d < Dn; d++) acc += qsm[d] * Wq[(h * Dn + d) * DKn + k];
        qhs[t] = acc;
    }
    __syncthreads();
    {
        int i = t;
#pragma unroll
        for (int h = 0; h < Hn; h++) {
            const float* gk = g_Gk + (h * Dn + i) * DKn;
            const float* qh = qhs + h * DKn;
            float s = 0.f;
#pragma unroll
            for (int k = 0; k < DKn; k++) s += qh[k] * gk[k];
            g_Rk[((size_t)b * Hn + h) * Dn + i] = s;
        }
    }
}

// ---------------- Kernel 2: main. 128 thr (4 warps), occ 5 (unchanged champion) -----------
#define SM_PD 8448
#define SM_MZ 8960
#define SMEM_BYTES (9024 * 4)

__global__ __launch_bounds__(128, 5)
void decoder_main(const float* __restrict__ emb, const int* __restrict__ lens,
                  const float* __restrict__ Wvp, const float* __restrict__ Wv,
                  const float* __restrict__ Wo, float* __restrict__ out) {
    extern __shared__ float sm[];
    __shared__ int sflag;

    int blk = blockIdx.x, b = blk >> 3, sp = blk & 7, t = threadIdx.x;
    int wrp = t >> 5, lane = t & 31;
    int h = lane & 7, q = lane >> 3;
    int len = lens[b];
    int cnt = min(len - sp * RPS, RPS);
    int ntiles = (cnt > 0) ? ((cnt + TLC - 1) >> 5) : 0;
    const float* embp = emb + (size_t)b * (Ln * Dn) + (size_t)sp * RPS * Dn;

    float* wbuf = sm + wrp * WTILE;
    float* pd   = sm + SM_PD + wrp * 128;
    float* sMZ  = sm + SM_MZ;
    uint32_t wdst = (uint32_t)__cvta_generic_to_shared(wbuf) + (uint32_t)lane * 16;

    ull rk[16];
    {
        const float* rbase = g_Rk + ((size_t)b * Hn + h) * Dn + 4 * q;
#pragma unroll
        for (int j = 0; j < 8; j++) {
            ulonglong2 v = *(const ulonglong2*)(rbase + 16 * j);
            rk[2 * j] = v.x; rk[2 * j + 1] = v.y;
        }
    }

    float m = -30000.f, Z = 0.f;
    ull w0[Hn], w1[Hn];
#pragma unroll
    for (int i = 0; i < Hn; i++) { w0[i] = 0ull; w1[i] = 0ull; }

#define LD_STRIPE(tt, bufk)                                                              \
    do {                                                                                  \
        const float* _s = embp + (size_t)((tt) * TLC + wrp * 8) * Dn + lane * 4;          \
        uint32_t _d = wdst + (uint32_t)(bufk) * (8 * WSTR * 4);                           \
        _Pragma("unroll")                                                                 \
        for (int _i = 0; _i < 8; _i++)                                                    \
            asm volatile("cp.async.cg.shared.global [%0], [%1], 16;\n"                    \
                         :: "r"(_d + _i * (WSTR * 4)), "l"(_s + _i * Dn) : "memory");     \
        asm volatile("cp.async.commit_group;\n" ::: "memory");                            \
    } while (0)

    if (ntiles > 0) {
        LD_STRIPE(0, 0);
        if (ntiles > 1) LD_STRIPE(1, 1);

        for (int tt = 0; tt < ntiles; tt++) {
            if (tt + 1 < ntiles) asm volatile("cp.async.wait_group 1;\n" ::: "memory");
            else                 asm volatile("cp.async.wait_group 0;\n" ::: "memory");
            __syncwarp();
            const float* tb = wbuf + (tt & 1) * (8 * WSTR);
            int base = tt * TLC + wrp * 8;

            float s8[8];
#pragma unroll
            for (int i = 0; i < 8; i++) {
                const ulonglong2* rp = (const ulonglong2*)(tb + i * WSTR + 4 * q);
                ull a0 = 0ull, a1 = 0ull;
#pragma unroll
                for (int j = 0; j < 8; j++) {
                    ulonglong2 ev = rp[4 * j];
                    a0 = fma2(ev.x, rk[2 * j], a0);
                    a1 = fma2(ev.y, rk[2 * j + 1], a1);
                }
                float2 fa = unpack2(a0), fb = unpack2(a1);
                float sv = (fa.x + fa.y) + (fb.x + fb.y);
                sv += __shfl_xor_sync(0xffffffffu, sv, 8);
                sv += __shfl_xor_sync(0xffffffffu, sv, 16);
                s8[i] = (base + i < cnt) ? sv : -1e30f;
            }

            float tm = s8[0];
#pragma unroll
            for (int i = 1; i < 8; i++) tm = fmaxf(tm, s8[i]);
            float mn = fmaxf(m, tm);
            float f = ex2(m - mn);
            m = mn;
            float zs = 0.f;
#pragma unroll
            for (int i = 0; i < 8; i++) {
                s8[i] = (s8[i] > -1e29f) ? ex2(s8[i] - mn) : 0.f;
                zs += s8[i];
            }
            Z = Z * f + zs;

            *(float2*)(pd + q * 16 + 2 * h)       = make_float2(s8[q], s8[q]);
            *(float2*)(pd + (q + 4) * 16 + 2 * h) = make_float2(s8[q + 4], s8[q + 4]);
            __syncwarp();

#pragma unroll
            for (int hh = 0; hh < Hn; hh++) {
                float fh = __shfl_sync(0xffffffffu, f, hh);
                ull fp = pack2(fh, fh);
                w0[hh] = mul2(w0[hh], fp);
                w1[hh] = mul2(w1[hh], fp);
            }
#pragma unroll
            for (int i = 0; i < 8; i++) {
                ulonglong2 ev = *(const ulonglong2*)(tb + i * WSTR + 4 * lane);
                const ull* pdr = (const ull*)(pd + i * 16);
#pragma unroll
                for (int hh = 0; hh < Hn; hh++) {
                    w0[hh] = fma2(pdr[hh], ev.x, w0[hh]);
                    w1[hh] = fma2(pdr[hh], ev.y, w1[hh]);
                }
            }
            __syncwarp();
            if (tt + 2 < ntiles) LD_STRIPE(tt + 2, tt & 1);
        }
    }

    if (q == 0) { sMZ[wrp * 16 + h] = m; sMZ[wrp * 16 + 8 + h] = Z; }
    __syncthreads();
    {
        ulonglong2* Wm = (ulonglong2*)sm;
#pragma unroll
        for (int hh = 0; hh < Hn; hh++) {
            ulonglong2 v; v.x = w0[hh]; v.y = w1[hh];
            Wm[(wrp * 8 + hh) * 32 + lane] = v;
        }
    }
    __syncthreads();
    {
        int h2 = t >> 4, g = t & 15;
        float mc = sMZ[h2];
#pragma unroll
        for (int wv = 1; wv < 4; wv++) mc = fmaxf(mc, sMZ[wv * 16 + h2]);
        float fw[4], Zc = 0.f;
#pragma unroll
        for (int wv = 0; wv < 4; wv++) {
            fw[wv] = ex2(sMZ[wv * 16 + h2] - mc);
            Zc += sMZ[wv * 16 + 8 + h2] * fw[wv];
        }
        const float4* Wmf = (const float4*)sm;
        float* gp = g_part + (size_t)blk * 1040;
#pragma unroll
        for (int part = 0; part < 2; part++) {
            int dq = g + 16 * part;
            float4 acc = make_float4(0.f, 0.f, 0.f, 0.f);
#pragma unroll
            for (int wv = 0; wv < 4; wv++) {
                float4 v = Wmf[(wv * 8 + h2) * 32 + dq];
                acc.x += fw[wv] * v.x; acc.y += fw[wv] * v.y;
                acc.z += fw[wv] * v.z; acc.w += fw[wv] * v.w;
            }
            *(float4*)(gp + 16 + h2 * Dn + 4 * dq) = acc;
        }
        if (g == 0) { gp[h2] = mc; gp[8 + h2] = Zc; }
    }
    __syncthreads();

    __threadfence();
    if (t == 0) {
        int r = atomicAdd(&g_cnt[b], 1);
        sflag = (r == SPLIT - 1);
        if (r == SPLIT - 1) g_cnt[b] = 0;
    }
    __syncthreads();
    if (!sflag) return;
    __threadfence();

    int a = b & 7;
    float* cc   = sm;
    float* wfs  = sm + 64;
    float* vmid = sm + 64 + Hn * Dn;
    float* sCtx = vmid + Hn * Dn;
    const float* Pb = g_part + (size_t)(b * SPLIT) * 1040;

    if (t < 8) {
        float mm = -1e30f;
#pragma unroll
        for (int s = 0; s < SPLIT; s++) mm = fmaxf(mm, Pb[s * 1040 + t]);
        float as[SPLIT], Zt = 0.f;
#pragma unroll
        for (int s = 0; s < SPLIT; s++) {
            as[s] = ex2(Pb[s * 1040 + t] - mm);
            Zt += Pb[s * 1040 + 8 + t] * as[s];
        }
        float inv = 1.f / Zt;
#pragma unroll
        for (int s = 0; s < SPLIT; s++) cc[s * 8 + t] = as[s] * inv;
    }
    __syncthreads();
    {
#pragma unroll
        for (int hh = 0; hh < Hn; hh++) {
            int off = 16 + hh * Dn + t;
            float acc = 0.f;
#pragma unroll
            for (int s = 0; s < SPLIT; s++) acc += Pb[s * 1040 + off] * cc[s * 8 + hh];
            wfs[hh * Dn + t] = acc;
        }
    }
    __syncthreads();
    {
        float acc[Hn];
        float bias = (float)a * Wvp[Dn * Dn + t];
#pragma unroll
        for (int hh = 0; hh < Hn; hh++) acc[hh] = bias;
#pragma unroll 4
        for (int i = 0; i < Dn; i++) {
            float wv = Wvp[i * Dn + t];
#pragma unroll
            for (int hh = 0; hh < Hn; hh++) acc[hh] += wfs[hh * Dn + i] * wv;
        }
#pragma unroll
        for (int hh = 0; hh < Hn; hh++) vmid[hh * Dn + t] = acc[hh];
    }
    __syncthreads();
    {
        int hh = t >> 4, k = t & 15;
        const float* wvr = Wv + hh * Dn * DKn + k;
        const float* vm = vmid + hh * Dn;
        float acc = 0.f;
#pragma unroll 4
        for (int d = 0; d < Dn; d++) acc += vm[d] * wvr[d * DKn];
        sCtx[t] = acc;
    }
    __syncthreads();
    {
        float acc = 0.f;
#pragma unroll 4
        for (int j = 0; j < Hn * DKn; j++) acc += sCtx[j] * Wo[j * Dn + t];
        out[(size_t)b * Dn + t] = acc;
    }
}

// ---------------------------------------------------------------------------
extern "C" void kernel_launch(void* const* d_in, const int* in_sizes, int n_in,
                              void* d_out, int out_size) {
    const float* gc      = (const float*)d_in[0];
    const float* depot   = (const float*)d_in[1];
    const float* tbd     = (const float*)d_in[2];
    const float* loadv   = (const float*)d_in[3];
    const float* emb     = (const float*)d_in[4];
    const int*   lens    = (const int*)  d_in[5];
    const float* Wq_proj = (const float*)d_in[6];
    const float* Wk_proj = (const float*)d_in[7];
    const float* Wv_proj = (const float*)d_in[8];
    const float* Wq      = (const float*)d_in[9];
    const float* Wk      = (const float*)d_in[10];
    const float* Wv      = (const float*)d_in[11];
    const float* Wo      = (const float*)d_in[12];
    float* out = (float*)d_out;

    prepA<<<En + Hn, 256>>>(gc, depot, tbd, Wq_proj, Wk, Wk_proj);
    prepB<<<EA, 128>>>(loadv, Wq_proj, Wq);

    cudaFuncSetAttribute(decoder_main, cudaFuncAttributeMaxDynamicSharedMemorySize, SMEM_BYTES);
    decoder_main<<<EA * SPLIT, 128, SMEM_BYTES>>>(emb, lens, Wv_proj, Wv, Wo, out);
}